// round 3
// baseline (speedup 1.0000x reference)
#include <cuda_runtime.h>
#include <cstdint>

// x (512,1,64,64) f32, weights (4,4,3) f32 -> out (512,12,31,31) f32
#define B_   512
#define H_   64
#define W_   64
#define HO_  31
#define WO_  31
#define NK_  4
#define QW_  8                         // ceil(31/4) ow-groups of 4 patches
#define NTHREAD_ (B_ * HO_ * QW_)      // 126976 = 496 * 256 exactly

__global__ __launch_bounds__(256) void qconv_kernel(const float* __restrict__ x,
                                                    const float* __restrict__ w,
                                                    float* __restrict__ out) {
    // ---- fused coefficient computation (reduced-density-matrix algebra:
    //      only weights[k][0] = (theta,phi,omega) reach the observables) ----
    __shared__ float sc[24];           // [kernel][axis][{alpha,beta}]
    if (threadIdx.x < NK_) {
        int k = threadIdx.x;
        float th = w[k * 12 + 0];
        float ph = w[k * 12 + 1];
        float om = w[k * 12 + 2];
        float ct = cosf(th), st = sinf(th);
        float chh = cosf(0.5f * th);
        float c2 = chh * chh;
        float s2 = 1.0f - c2;
        float cpo = cosf(ph + om), spo = sinf(ph + om);
        float cmo = cosf(om - ph), smo = sinf(om - ph);
        sc[k * 6 + 0] = st * cosf(ph);
        sc[k * 6 + 1] = 2.0f * (c2 * cpo - s2 * cmo);
        sc[k * 6 + 2] = st * sinf(ph);
        sc[k * 6 + 3] = 2.0f * (c2 * spo + s2 * smo);
        sc[k * 6 + 4] = ct;
        sc[k * 6 + 5] = -2.0f * st * cosf(om);
    }
    __syncthreads();

    int tid = blockIdx.x * blockDim.x + threadIdx.x;   // grid sized exactly
    int q  = tid & 7;                  // ow-group: patches ow = 4q .. 4q+3
    int t  = tid >> 3;
    int oh = t % HO_;
    int b  = t / HO_;

    bool full = (q < 7);               // q==7 handles only 3 patches (ow 28..30)
    int npat = full ? 4 : 3;

    // 4 rows x 12 cols window: input cols 8q .. 8q+11 (q==7: zero-pad cols 64..67)
    const float* p = x + ((size_t)(b * H_ + oh * 2) * W_ + q * 8);

    float v0[12], v1[12], v2[12], v3[12];
#define LOAD12(dst, ptr)                                                   \
    {                                                                      \
        float4 A = *reinterpret_cast<const float4*>(ptr);                  \
        float4 Bq = *reinterpret_cast<const float4*>((ptr) + 4);           \
        float4 Cq = full ? *reinterpret_cast<const float4*>((ptr) + 8)     \
                         : make_float4(0.f, 0.f, 0.f, 0.f);                \
        dst[0]=A.x; dst[1]=A.y; dst[2]=A.z; dst[3]=A.w;                    \
        dst[4]=Bq.x; dst[5]=Bq.y; dst[6]=Bq.z; dst[7]=Bq.w;                \
        dst[8]=Cq.x; dst[9]=Cq.y; dst[10]=Cq.z; dst[11]=Cq.w;              \
    }
    LOAD12(v0, p);
    LOAD12(v1, p + W_);
    LOAD12(v2, p + 2 * W_);
    LOAD12(v3, p + 3 * W_);
#undef LOAD12

    // Per-column: a = v0^2+v2^2 (rows with +sign), bb = v1^2+v3^2 (-sign),
    //             C = v0*v3 + v1*v2 (off-diagonal cross terms, CNOT-ring folded)
    float PS[6], Qd[6], PC[6];
#pragma unroll
    for (int pr = 0; pr < 6; pr++) {
        int c0 = 2 * pr, c1 = 2 * pr + 1;
        float a0 = fmaf(v2[c0], v2[c0], v0[c0] * v0[c0]);
        float b0 = fmaf(v3[c0], v3[c0], v1[c0] * v1[c0]);
        float a1 = fmaf(v2[c1], v2[c1], v0[c1] * v0[c1]);
        float b1 = fmaf(v3[c1], v3[c1], v1[c1] * v1[c1]);
        float C0 = fmaf(v0[c0], v3[c0], v1[c0] * v2[c0]);
        float C1 = fmaf(v0[c1], v3[c1], v1[c1] * v2[c1]);
        PS[pr] = (a0 + b0) + (a1 + b1);          // pair norm
        Qd[pr] = (a0 - b0) - (a1 - b1);          // pair signed diag (cols +,-)
        PC[pr] = C0 + C1;                        // pair cross
    }

    // out[b, 3k+a, oh, ow]; patch j writes column 4q+j of 12 channel planes
    float* o = out + (size_t)b * (12 * HO_ * WO_) + (size_t)oh * WO_ + q * 4;
#pragma unroll
    for (int j = 0; j < 4; j++) {
        if (j >= npat) break;
        float nrm = PS[j] + PS[j + 1];
        float d   = Qd[j] - Qd[j + 1];           // col signs within patch: +,-,-,+
        float cc  = PC[j] + PC[j + 1];
        float inv = 1.0f / fmaxf(nrm, 1e-30f);
        d  *= inv;
        cc *= inv;
#pragma unroll
        for (int ch = 0; ch < 12; ch++) {
            o[(size_t)ch * (HO_ * WO_) + j] = fmaf(sc[2 * ch], d, sc[2 * ch + 1] * cc);
        }
    }
}

extern "C" void kernel_launch(void* const* d_in, const int* in_sizes, int n_in,
                              void* d_out, int out_size) {
    const float* x = (const float*)d_in[0];
    const float* w = (const float*)d_in[1];
    if (n_in >= 2 && in_sizes[0] == NK_ * 4 * 3) {  // defensive input-order swap
        x = (const float*)d_in[1];
        w = (const float*)d_in[0];
    }
    qconv_kernel<<<NTHREAD_ / 256, 256>>>(x, w, (float*)d_out);
}

// round 4
// speedup vs baseline: 1.6617x; 1.6617x over previous
#include <cuda_runtime.h>
#include <cstdint>

// x (512,1,64,64) f32, weights (4,4,3) f32 -> out (512,12,31,31) f32
#define B_   512
#define H_   64
#define W_   64
#define HO_  31
#define WO_  31
#define NK_  4
#define QW2_ 16                          // ow-pairs: ow = 2q, 2q+1 (q=15 -> only ow=30)
#define NTHREAD_ (B_ * HO_ * QW2_)       // 253952 = 992 * 256 exactly

__global__ __launch_bounds__(256) void qconv_kernel(const float* __restrict__ x,
                                                    const float* __restrict__ w,
                                                    float* __restrict__ out) {
    // Fused coefficients (reduced-density-matrix algebra: only weights[k][0]
    // = (theta,phi,omega) reach the observables). e_a = alpha_a*d + beta_a*cc.
    __shared__ float sc[24];
    if (threadIdx.x < NK_) {
        int k = threadIdx.x;
        float th = w[k * 12 + 0];
        float ph = w[k * 12 + 1];
        float om = w[k * 12 + 2];
        float ct = cosf(th), st = sinf(th);
        float chh = cosf(0.5f * th);
        float c2 = chh * chh;
        float s2 = 1.0f - c2;
        float cpo = cosf(ph + om), spo = sinf(ph + om);
        float cmo = cosf(om - ph), smo = sinf(om - ph);
        sc[k * 6 + 0] = st * cosf(ph);
        sc[k * 6 + 1] = 2.0f * (c2 * cpo - s2 * cmo);
        sc[k * 6 + 2] = st * sinf(ph);
        sc[k * 6 + 3] = 2.0f * (c2 * spo + s2 * smo);
        sc[k * 6 + 4] = ct;
        sc[k * 6 + 5] = -2.0f * st * cosf(om);
    }
    __syncthreads();

    int tid = blockIdx.x * blockDim.x + threadIdx.x;   // grid exact, no bounds check
    int q  = tid & 15;                 // patches ow = 2q, 2q+1
    int t  = tid >> 4;
    int oh = t % HO_;
    int b  = t / HO_;

    bool full = (q < 15);              // q==15: only ow=30 (cols 60..63)

    // 4 rows x 6 cols window starting at input col 4q (16B-aligned)
    const float* p = x + ((size_t)(b * H_ + oh * 2) * W_ + q * 4);

    float v[4][6];
#pragma unroll
    for (int r = 0; r < 4; r++) {
        float4 A = *reinterpret_cast<const float4*>(p + r * W_);
        v[r][0] = A.x; v[r][1] = A.y; v[r][2] = A.z; v[r][3] = A.w;
        if (full) {
            float2 Bq = *reinterpret_cast<const float2*>(p + r * W_ + 4);
            v[r][4] = Bq.x; v[r][5] = Bq.y;
        } else {
            v[r][4] = 0.f; v[r][5] = 0.f;
        }
    }

    // Per-column: s = sum v^2 (norm), dd = (v0^2+v2^2)-(v1^2+v3^2) (signed diag,
    // row signs from CNOT-ring parity), C = v0*v3 + v1*v2 (off-diag partner r^3).
    float s[6], dd[6], C[6];
#pragma unroll
    for (int c = 0; c < 6; c++) {
        float a  = fmaf(v[2][c], v[2][c], v[0][c] * v[0][c]);
        float bb = fmaf(v[3][c], v[3][c], v[1][c] * v[1][c]);
        s[c]  = a + bb;
        dd[c] = a - bb;
        C[c]  = fmaf(v[0][c], v[3][c], v[1][c] * v[2][c]);
    }

    // out[b, 3k+a, oh, ow]; column signs within a patch: +,-,-,+
    float* o = out + (size_t)b * (12 * HO_ * WO_) + (size_t)oh * WO_ + q * 2;
#pragma unroll
    for (int j = 0; j < 2; j++) {
        if (j == 1 && !full) break;
        float nrm = (s[2*j]  + s[2*j+1])  + (s[2*j+2]  + s[2*j+3]);
        float d   = (dd[2*j] - dd[2*j+1]) - (dd[2*j+2] - dd[2*j+3]);
        float cc  = (C[2*j]  + C[2*j+1])  + (C[2*j+2]  + C[2*j+3]);
        float inv = 1.0f / fmaxf(nrm, 1e-30f);
        d  *= inv;
        cc *= inv;
#pragma unroll
        for (int ch = 0; ch < 12; ch++) {
            o[(size_t)ch * (HO_ * WO_) + j] = fmaf(sc[2 * ch], d, sc[2 * ch + 1] * cc);
        }
    }
}

extern "C" void kernel_launch(void* const* d_in, const int* in_sizes, int n_in,
                              void* d_out, int out_size) {
    const float* x = (const float*)d_in[0];
    const float* w = (const float*)d_in[1];
    if (n_in >= 2 && in_sizes[0] == NK_ * 4 * 3) {  // defensive input-order swap
        x = (const float*)d_in[1];
        w = (const float*)d_in[0];
    }
    qconv_kernel<<<NTHREAD_ / 256, 256>>>(x, w, (float*)d_out);
}

// round 5
// speedup vs baseline: 1.9791x; 1.1910x over previous
#include <cuda_runtime.h>
#include <cstdint>

// x (512,1,64,64) f32, weights (4,4,3) f32 -> out (512,12,31,31) f32
#define B_   512
#define H_   64
#define W_   64
#define HO_  31
#define WO_  31
#define NK_  4
#define TOTAL_ (B_ * HO_ * WO_)   // 492032 = 1922 * 256 exactly

__device__ __forceinline__ float frcp_approx(float x) {
    float r;
    asm("rcp.approx.f32 %0, %1;" : "=f"(r) : "f"(x));
    return r;
}

__global__ __launch_bounds__(256) void qconv_kernel(const float* __restrict__ x,
                                                    const float* __restrict__ w,
                                                    float* __restrict__ out) {
    // Fused coefficients (reduced-density-matrix algebra: only weights[k][0]
    // = (theta,phi,omega) reach the observables). e_a = alpha_a*d + beta_a*cc.
    __shared__ float sc[24];
    if (threadIdx.x < NK_) {
        int k = threadIdx.x;
        float th = w[k * 12 + 0];
        float ph = w[k * 12 + 1];
        float om = w[k * 12 + 2];
        float ct = cosf(th), st = sinf(th);
        float chh = cosf(0.5f * th);
        float c2 = chh * chh;
        float s2 = 1.0f - c2;
        float cpo = cosf(ph + om), spo = sinf(ph + om);
        float cmo = cosf(om - ph), smo = sinf(om - ph);
        sc[k * 6 + 0] = st * cosf(ph);
        sc[k * 6 + 1] = 2.0f * (c2 * cpo - s2 * cmo);
        sc[k * 6 + 2] = st * sinf(ph);
        sc[k * 6 + 3] = 2.0f * (c2 * spo + s2 * smo);
        sc[k * 6 + 4] = ct;
        sc[k * 6 + 5] = -2.0f * st * cosf(om);
    }
    __syncthreads();

    int tid = blockIdx.x * blockDim.x + threadIdx.x;   // grid exact: no bounds check
    int ow = tid % WO_;
    int t  = tid / WO_;
    int oh = t % HO_;
    int b  = t / HO_;

    const float* p = x + ((size_t)(b * H_ + oh * 2) * W_ + ow * 2);

    // 8 independent LDG.64 issued up front (max MLP)
    float2 a0 = *reinterpret_cast<const float2*>(p);
    float2 b0 = *reinterpret_cast<const float2*>(p + 2);
    float2 a1 = *reinterpret_cast<const float2*>(p + W_);
    float2 b1 = *reinterpret_cast<const float2*>(p + W_ + 2);
    float2 a2 = *reinterpret_cast<const float2*>(p + 2 * W_);
    float2 b2 = *reinterpret_cast<const float2*>(p + 2 * W_ + 2);
    float2 a3 = *reinterpret_cast<const float2*>(p + 3 * W_);
    float2 b3 = *reinterpret_cast<const float2*>(p + 3 * W_ + 2);

    // CNOT-ring folded to index algebra. Per column c (sign pattern +,-,-,+):
    //   a_c = v0^2 + v2^2, b_c = v1^2 + v3^2  (rows with MSB 0 / 1 after ring)
    //   C_c = v0*v3 + v1*v2                   (off-diagonal partner i ^ 12)
    // nrm = sum(a+b); d = (a-b) signed by column; cc = C signed-summed likewise.
    float A0 = fmaf(a2.x, a2.x, a0.x * a0.x), B0 = fmaf(a3.x, a3.x, a1.x * a1.x);
    float A1 = fmaf(a2.y, a2.y, a0.y * a0.y), B1 = fmaf(a3.y, a3.y, a1.y * a1.y);
    float A2 = fmaf(b2.x, b2.x, b0.x * b0.x), B2 = fmaf(b3.x, b3.x, b1.x * b1.x);
    float A3 = fmaf(b2.y, b2.y, b0.y * b0.y), B3 = fmaf(b3.y, b3.y, b1.y * b1.y);

    float C0 = fmaf(a0.x, a3.x, a1.x * a2.x);
    float C1 = fmaf(a0.y, a3.y, a1.y * a2.y);
    float C2 = fmaf(b0.x, b3.x, b1.x * b2.x);
    float C3 = fmaf(b0.y, b3.y, b1.y * b2.y);

    float nrm = ((A0 + B0) + (A1 + B1)) + ((A2 + B2) + (A3 + B3));
    float d   = ((A0 - B0) - (A1 - B1)) - ((A2 - B2) - (A3 - B3));
    float cc  = (C0 + C1) + (C2 + C3);

    float inv = frcp_approx(fmaxf(nrm, 1e-30f));
    d  *= inv;
    cc *= inv;

    // out[b, 3k+axis, oh, ow]: consecutive tids hit consecutive addresses per channel
    float* o = out + (size_t)b * (12 * HO_ * WO_) + (size_t)oh * WO_ + ow;
#pragma unroll
    for (int ch = 0; ch < 12; ch++) {
        o[(size_t)ch * (HO_ * WO_)] = fmaf(sc[2 * ch], d, sc[2 * ch + 1] * cc);
    }
}

extern "C" void kernel_launch(void* const* d_in, const int* in_sizes, int n_in,
                              void* d_out, int out_size) {
    const float* x = (const float*)d_in[0];
    const float* w = (const float*)d_in[1];
    if (n_in >= 2 && in_sizes[0] == NK_ * 4 * 3) {  // defensive input-order swap
        x = (const float*)d_in[1];
        w = (const float*)d_in[0];
    }
    qconv_kernel<<<TOTAL_ / 256, 256>>>(x, w, (float*)d_out);
}